// round 15
// baseline (speedup 1.0000x reference)
#include <cuda_runtime.h>
#include <cuda_fp16.h>
#include <cstdint>

#define NBATCH 4
#define HEADS  16
#define NH     (NBATCH * HEADS)
#define QL     2048
#define KVL    2048
#define HD     64
#define ED     1024
#define K2E    0.045084220027780106f   /* (1/sqrt(1024)) * log2(e) */

#define BQ 128
#define BN 64
#define NCHUNK (KVL / BN)
#define PH_PITCH 36   /* words (half2 pairs); %32==4 -> conflict-free frags */

/* pre-converted fp16 operand layouts (device scratch), k-INTERLEAVED:
   within each 8-word k-group, stored[2c]=orig[c], stored[2c+1]=orig[c+4],
   so every mma fragment pair is one LDS.64.                                 */
static __device__ uint32_t g_Qh[(size_t)NH * QL * 32];          /* [nh][q][d/2]  */
static __device__ uint32_t g_Kh[(size_t)NH * KVL * 32];         /* [nh][kv][d/2] */
static __device__ uint32_t g_Vt[(size_t)NH * HD * (KVL / 2)];   /* [nh][d][rp]   */
static __device__ uint32_t g_Xh[(size_t)NBATCH * QL * (ED / 2)];/* attn out fp16 */
static __device__ uint32_t g_Wh[(size_t)ED * (ED / 2)];         /* W fp16        */
static __device__ uint32_t g_maskbits[NBATCH * QL * (KVL / 32)];

/* ----------------------------- small helpers ----------------------------- */
__device__ __forceinline__ int kperm(int w) {   /* k-group interleave */
    int u = w & 7;
    return (w & ~7) | (u < 4 ? 2 * u : 2 * u - 7);
}
__device__ __forceinline__ uint32_t pack2(float lo, float hi) {
    __half2 h = __floats2half2_rn(lo, hi);
    return *(uint32_t*)&h;
}
__device__ __forceinline__ float ex2f(float x) {
    float r;
    asm("ex2.approx.f32 %0, %1;" : "=f"(r) : "f"(x));
    return r;
}
__device__ __forceinline__ uint32_t smem_u32(const void* p) {
    uint32_t a;
    asm("{ .reg .u64 t; cvta.to.shared.u64 t, %1; cvt.u32.u64 %0, t; }"
        : "=r"(a) : "l"(p));
    return a;
}
__device__ __forceinline__ void cp16(uint32_t dst, const void* src) {
    asm volatile("cp.async.cg.shared.global [%0], [%1], 16;"
                 :: "r"(dst), "l"(src) : "memory");
}
#define CP_COMMIT() asm volatile("cp.async.commit_group;" ::: "memory")
#define CP_WAIT0()  asm volatile("cp.async.wait_group 0;" ::: "memory")

/* D(16x8,f32) += A(16x16,f16) * B(16x8,f16)  —  m16n8k16 row.col */
__device__ __forceinline__ void mma16(float* d, const uint32_t* a,
                                      uint32_t b0, uint32_t b1) {
    asm volatile(
        "mma.sync.aligned.m16n8k16.row.col.f32.f16.f16.f32 "
        "{%0,%1,%2,%3}, {%4,%5,%6,%7}, {%8,%9}, {%0,%1,%2,%3};"
        : "+f"(d[0]), "+f"(d[1]), "+f"(d[2]), "+f"(d[3])
        : "r"(a[0]), "r"(a[1]), "r"(a[2]), "r"(a[3]), "r"(b0), "r"(b1));
}

/* ------------------------------ pre-kernels ------------------------------ */
__global__ void maskpack(const int* __restrict__ M) {
    int warpid = (blockIdx.x * blockDim.x + threadIdx.x) >> 5;
    int lane = threadIdx.x & 31;
    size_t base = (size_t)warpid * 8;
    #pragma unroll
    for (int t = 0; t < 8; t++) {
        size_t wd = base + t;
        int v = M[wd * 32 + lane];
        uint32_t bits = __ballot_sync(0xffffffffu, v != 0);
        if (lane == 0) g_maskbits[wd] = bits;
    }
}

/* Q,K -> head-major fp16 rows, k-interleaved */
__global__ __launch_bounds__(256) void convQK(const float* __restrict__ Q,
                                              const float* __restrict__ K) {
    int nh = blockIdx.y, n = nh >> 4, h = nh & 15;
    int r0 = blockIdx.x * 128;
    int tid = threadIdx.x;
    const float* qs = Q + ((size_t)n * QL + r0) * ED + h * HD;
    const float* ks = K + ((size_t)n * KVL + r0) * ED + h * HD;
    uint32_t* qd = g_Qh + ((size_t)nh * QL + r0) * 32;
    uint32_t* kd = g_Kh + ((size_t)nh * KVL + r0) * 32;
    #pragma unroll
    for (int j = 0; j < 8; j++) {
        int flat = tid + 256 * j, r = flat >> 4, d0 = (flat & 15) * 4;
        int w0 = d0 / 2;
        float4 a = *(const float4*)(qs + (size_t)r * ED + d0);
        qd[r * 32 + kperm(w0)]     = pack2(a.x, a.y);
        qd[r * 32 + kperm(w0 + 1)] = pack2(a.z, a.w);
        float4 b = *(const float4*)(ks + (size_t)r * ED + d0);
        kd[r * 32 + kperm(w0)]     = pack2(b.x, b.y);
        kd[r * 32 + kperm(w0 + 1)] = pack2(b.z, b.w);
    }
}

/* V -> transposed half2 image, kv-word interleaved:
   stored word(d, kperm(rp)) = {V[2rp][d], V[2rp+1][d]} */
__global__ __launch_bounds__(256) void convV(const float* __restrict__ V) {
    int nh = blockIdx.y, n = nh >> 4, h = nh & 15;
    int rp = blockIdx.x * 32 + (threadIdx.x & 31);
    int w = threadIdx.x >> 5;
    int rpp = kperm(rp);
    const float* vs = V + (size_t)n * KVL * ED + h * HD;
    uint32_t* vd = g_Vt + (size_t)nh * HD * (KVL / 2);
    #pragma unroll
    for (int j = 0; j < 2; j++) {
        int d0 = (w * 2 + j) * 4;
        float4 a = *(const float4*)(vs + (size_t)(2 * rp) * ED + d0);
        float4 b = *(const float4*)(vs + (size_t)(2 * rp + 1) * ED + d0);
        vd[(d0 + 0) * (KVL / 2) + rpp] = pack2(a.x, b.x);
        vd[(d0 + 1) * (KVL / 2) + rpp] = pack2(a.y, b.y);
        vd[(d0 + 2) * (KVL / 2) + rpp] = pack2(a.z, b.z);
        vd[(d0 + 3) * (KVL / 2) + rpp] = pack2(a.w, b.w);
    }
}

__global__ void convW(const float* __restrict__ W) {
    int flat = blockIdx.x * 256 + threadIdx.x;   /* 262144 float4s */
    float4 v = *(const float4*)(W + (size_t)flat * 4);
    int n = flat >> 8;
    int w0 = (flat & 255) * 2;
    g_Wh[n * 512 + kperm(w0)]     = pack2(v.x, v.y);
    g_Wh[n * 512 + kperm(w0 + 1)] = pack2(v.z, v.w);
}

/* -------------------- fp16 mma.sync flash attention ---------------------- */
/* BQ=128, 8 warps, occ 2. cp.async staging of k-interleaved fp16 layouts;
   every fragment load is one LDS.64. P register-resident.                  */
__global__ __launch_bounds__(256, 2) void attn_mma() {
    extern __shared__ uint32_t sm[];
    uint32_t* smK = sm;            /* 2 bufs @ 0, 2304 (words)  */
    uint32_t* smV = sm + 4608;     /* 2 bufs @ 4608, 6912       */
    uint32_t* QS  = sm + 9216;     /* [128][36] Q fragments     */
    const uint32_t sbase = smem_u32(sm);
    const uint32_t KSb = sbase;
    const uint32_t VSb = sbase + 4608 * 4;
    const uint32_t QSb = sbase + 9216 * 4;

    const int tid = threadIdx.x, w = tid >> 5, lane = tid & 31;
    const int g = lane >> 2, c = lane & 3;
    const int nh = blockIdx.y, n = nh >> 4;
    const int q0 = blockIdx.x * BQ;

    const uint32_t* Qg = g_Qh + ((size_t)nh * QL + q0) * 32;
    const uint32_t* Kg = g_Kh + (size_t)nh * KVL * 32;
    const uint32_t* Vg = g_Vt + (size_t)nh * HD * (KVL / 2);

    /* issue Q (128 rows x 128B) + K/V chunk 0 into buf 0 */
    #pragma unroll
    for (int i = 0; i < 4; i++) {
        int cid = tid + 256 * i, r = cid >> 3, seg = cid & 7;
        cp16(QSb + (r * PH_PITCH + seg * 4) * 4, Qg + r * 32 + seg * 4);
    }
    #pragma unroll
    for (int i = 0; i < 2; i++) {
        int cid = tid + 256 * i, r = cid >> 3, seg = cid & 7;
        cp16(KSb + (r * PH_PITCH + seg * 4) * 4, Kg + r * 32 + seg * 4);
        cp16(VSb + (r * PH_PITCH + seg * 4) * 4,
             Vg + (size_t)r * (KVL / 2) + seg * 4);
    }
    CP_COMMIT();
    CP_WAIT0();
    __syncthreads();

    /* resident Q A-fragments: 4 ks16 x 4 regs, LDS.64 pairs */
    uint32_t aQ[4][4];
    {
        int rb = w * 16;
        #pragma unroll
        for (int ks = 0; ks < 4; ks++) {
            const uint32_t* p0 = QS + (rb + g) * PH_PITCH + ks * 8 + 2 * c;
            uint2 lo = *(const uint2*)p0;
            uint2 hi = *(const uint2*)(p0 + 8 * PH_PITCH);
            aQ[ks][0] = lo.x; aQ[ks][1] = hi.x;
            aQ[ks][2] = lo.y; aQ[ks][3] = hi.y;
        }
    }

    float Oa[8][4];
    #pragma unroll
    for (int i = 0; i < 8; i++)
        #pragma unroll
        for (int j = 0; j < 4; j++) Oa[i][j] = 0.0f;
    float rs0 = 0.0f, rs1 = 0.0f;

    const unsigned long long* mbase = (const unsigned long long*)g_maskbits;
    const unsigned long long* mp0 =
        mbase + (size_t)(n * QL + q0 + w * 16 + g) * 32;
    const unsigned long long* mp1 = mp0 + 8 * 32;

    for (int ch = 0; ch < NCHUNK; ch++) {
        const int p = ch & 1;
        const uint32_t* KS = smK + p * 2304;
        const uint32_t* VS = smV + p * 2304;

        if (ch > 0) {
            CP_WAIT0();
            __syncthreads();
        }
        if (ch + 1 < NCHUNK) {
            const uint32_t kb2 = KSb + (1 - p) * 2304 * 4;
            const uint32_t vb2 = VSb + (1 - p) * 2304 * 4;
            const uint32_t* Kn = Kg + (size_t)(ch + 1) * 64 * 32;
            const uint32_t* Vn = Vg + (ch + 1) * 32;
            #pragma unroll
            for (int i = 0; i < 2; i++) {
                int cid = tid + 256 * i, r = cid >> 3, seg = cid & 7;
                cp16(kb2 + (r * PH_PITCH + seg * 4) * 4, Kn + r * 32 + seg * 4);
                cp16(vb2 + (r * PH_PITCH + seg * 4) * 4,
                     Vn + (size_t)r * (KVL / 2) + seg * 4);
            }
            CP_COMMIT();
        }

        unsigned long long m0 = mp0[ch];
        unsigned long long m1 = mp1[ch];

        /* ---- per nsp (16 kv): QK -> softmax (registers) -> PV */
        #pragma unroll
        for (int nsp = 0; nsp < 4; nsp++) {
            float S[2][4];
            #pragma unroll
            for (int nn = 0; nn < 2; nn++)
                #pragma unroll
                for (int j = 0; j < 4; j++) S[nn][j] = 0.0f;

            #pragma unroll
            for (int ks = 0; ks < 4; ks++) {
                #pragma unroll
                for (int nn = 0; nn < 2; nn++) {
                    int ns = nsp * 2 + nn;
                    uint2 bb = *(const uint2*)(KS + (ns * 8 + g) * PH_PITCH
                                               + ks * 8 + 2 * c);
                    mma16(S[nn], aQ[ks], bb.x, bb.y);
                }
            }

            uint32_t aP[4];
            #pragma unroll
            for (int nn = 0; nn < 2; nn++) {
                int ns = nsp * 2 + nn;
                int sh = ns * 8 + 2 * c;
                uint32_t bm0 = (uint32_t)(m0 >> sh);
                uint32_t bm1 = (uint32_t)(m1 >> sh);
                float e0 = (bm0 & 1u) ? ex2f(S[nn][0] * K2E) : 0.0f;
                float e1 = (bm0 & 2u) ? ex2f(S[nn][1] * K2E) : 0.0f;
                float e2 = (bm1 & 1u) ? ex2f(S[nn][2] * K2E) : 0.0f;
                float e3 = (bm1 & 2u) ? ex2f(S[nn][3] * K2E) : 0.0f;
                rs0 += e0 + e1;
                rs1 += e2 + e3;
                aP[2 * nn]     = pack2(e0, e1);
                aP[2 * nn + 1] = pack2(e2, e3);
            }

            #pragma unroll
            for (int ds = 0; ds < 8; ds++) {
                uint2 vv = *(const uint2*)(VS + (ds * 8 + g) * PH_PITCH
                                           + nsp * 8 + 2 * c);
                mma16(Oa[ds], aP, vv.x, vv.y);
            }
        }
    }

    /* row-sum reduce across quad, normalize, write fp16 (k-interleaved) */
    rs0 += __shfl_xor_sync(0xffffffffu, rs0, 1);
    rs0 += __shfl_xor_sync(0xffffffffu, rs0, 2);
    rs1 += __shfl_xor_sync(0xffffffffu, rs1, 1);
    rs1 += __shfl_xor_sync(0xffffffffu, rs1, 2);
    float inv0 = 1.0f / rs0, inv1 = 1.0f / rs1;

    uint32_t* x0 = g_Xh + (size_t)(n * QL + q0 + w * 16 + g) * 512
                 + (nh & 15) * 32;
    uint32_t* x1 = x0 + 8 * 512;
    #pragma unroll
    for (int ds = 0; ds < 8; ds++) {
        int pos = kperm(ds * 4 + c);
        x0[pos] = pack2(Oa[ds][0] * inv0, Oa[ds][1] * inv0);
        x1[pos] = pack2(Oa[ds][2] * inv1, Oa[ds][3] * inv1);
    }
}

/* ------ projection Y = Xh Wh^T + b : cp.async double-buffer, KT=64 ------- */
__global__ __launch_bounds__(256, 2) void proj_mma(const float* __restrict__ bias,
                                                   float* __restrict__ Y)
{
    extern __shared__ uint32_t ps[];
    uint32_t* XB = ps;             /* 2 bufs @ 0, 4608 (words) */
    uint32_t* WB = ps + 9216;      /* 2 bufs @ 9216, 13824     */
    const uint32_t sb = smem_u32(ps);
    const uint32_t XBb = sb, WBb = sb + 9216 * 4;

    const int tid = threadIdx.x, w = tid >> 5, lane = tid & 31;
    const int g = lane >> 2, c = lane & 3;
    const int wm = w & 3, wn = w >> 2;
    const int m0 = blockIdx.y * 128, n0 = blockIdx.x * 128;

    const uint32_t* Xg = g_Xh + (size_t)m0 * 512;
    const uint32_t* Wg = g_Wh + (size_t)n0 * 512;

    float D[2][8][4];
    #pragma unroll
    for (int a = 0; a < 2; a++)
        #pragma unroll
        for (int i = 0; i < 8; i++)
            #pragma unroll
            for (int j = 0; j < 4; j++) D[a][i][j] = 0.0f;

    /* stage k-tile 0 into buf 0 */
    #pragma unroll
    for (int i = 0; i < 4; i++) {
        int cid = tid + 256 * i, r = cid >> 3, seg = cid & 7;
        cp16(XBb + (r * PH_PITCH + seg * 4) * 4, Xg + r * 512 + seg * 4);
        cp16(WBb + (r * PH_PITCH + seg * 4) * 4, Wg + r * 512 + seg * 4);
    }
    CP_COMMIT();

    for (int kt = 0; kt < 16; kt++) {
        const int p = kt & 1;
        CP_WAIT0();
        __syncthreads();
        if (kt + 1 < 16) {
            const uint32_t xb2 = XBb + (1 - p) * 4608 * 4;
            const uint32_t wb2 = WBb + (1 - p) * 4608 * 4;
            int koff = (kt + 1) * 32;
            #pragma unroll
            for (int i = 0; i < 4; i++) {
                int cid = tid + 256 * i, r = cid >> 3, seg = cid & 7;
                cp16(xb2 + (r * PH_PITCH + seg * 4) * 4,
                     Xg + r * 512 + koff + seg * 4);
                cp16(wb2 + (r * PH_PITCH + seg * 4) * 4,
                     Wg + r * 512 + koff + seg * 4);
            }
            CP_COMMIT();
        }

        const uint32_t* XS = XB + p * 4608;
        const uint32_t* WS = WB + p * 4608;
        #pragma unroll
        for (int ks = 0; ks < 4; ks++) {
            uint32_t A[2][4];
            #pragma unroll
            for (int mi = 0; mi < 2; mi++) {
                int rb = wm * 32 + mi * 16;
                const uint32_t* p0 = XS + (rb + g) * PH_PITCH + ks * 8 + 2 * c;
                uint2 lo = *(const uint2*)p0;
                uint2 hi = *(const uint2*)(p0 + 8 * PH_PITCH);
                A[mi][0] = lo.x; A[mi][1] = hi.x;
                A[mi][2] = lo.y; A[mi][3] = hi.y;
            }
            #pragma unroll
            for (int ns = 0; ns < 8; ns++) {
                uint2 bb = *(const uint2*)(WS + (wn * 64 + ns * 8 + g) * PH_PITCH
                                           + ks * 8 + 2 * c);
                mma16(D[0][ns], A[0], bb.x, bb.y);
                mma16(D[1][ns], A[1], bb.x, bb.y);
            }
        }
        __syncthreads();   /* reads of buf p done before its next overwrite */
    }

    #pragma unroll
    for (int mi = 0; mi < 2; mi++) {
        int row0 = m0 + wm * 32 + mi * 16 + g;
        #pragma unroll
        for (int ns = 0; ns < 8; ns++) {
            int col = n0 + wn * 64 + ns * 8 + 2 * c;
            float2 bv = *(const float2*)(bias + col);
            *(float2*)(Y + (size_t)row0 * ED + col) =
                make_float2(D[mi][ns][0] + bv.x, D[mi][ns][1] + bv.y);
            *(float2*)(Y + (size_t)(row0 + 8) * ED + col) =
                make_float2(D[mi][ns][2] + bv.x, D[mi][ns][3] + bv.y);
        }
    }
}

/* --------------------------------- launch -------------------------------- */
extern "C" void kernel_launch(void* const* d_in, const int* in_sizes, int n_in,
                              void* d_out, int out_size)
{
    const float* q    = (const float*)d_in[0];
    const float* k    = (const float*)d_in[1];
    const float* v    = (const float*)d_in[2];
    const int*   mask = (const int*)  d_in[3];
    const float* W    = (const float*)d_in[4];
    const float* b    = (const float*)d_in[5];
    float* out = (float*)d_out;

    const int smem_attn = 13824 * 4;   /* 55296 */
    const int smem_proj = 18432 * 4;   /* 73728 */
    cudaFuncSetAttribute(attn_mma, cudaFuncAttributeMaxDynamicSharedMemorySize, smem_attn);
    cudaFuncSetAttribute(proj_mma, cudaFuncAttributeMaxDynamicSharedMemorySize, smem_proj);

    maskpack<<<8192, 256>>>(mask);
    convQK<<<dim3(16, 64), 256>>>(q, k);
    convV<<<dim3(32, 64), 256>>>(v);
    convW<<<1024, 256>>>(W);

    attn_mma<<<dim3(QL / BQ, NH), 256, smem_attn>>>();

    proj_mma<<<dim3(ED / 128, (NBATCH * QL) / 128), 256, smem_proj>>>(b, out);
}

// round 16
// speedup vs baseline: 1.1147x; 1.1147x over previous
#include <cuda_runtime.h>
#include <cuda_fp16.h>
#include <cstdint>

#define NBATCH 4
#define HEADS  16
#define NH     (NBATCH * HEADS)
#define QL     2048
#define KVL    2048
#define HD     64
#define ED     1024
#define K2E    0.045084220027780106f   /* (1/sqrt(1024)) * log2(e) */

#define BQ 128
#define BN 64
#define NCHUNK (KVL / BN)
#define PH_PITCH 36   /* words (half2 pairs); %32==4 -> conflict-free ldmatrix */
#define P4 (PH_PITCH * 4)

/* pre-converted fp16 operand layouts (device scratch) — R14 layouts */
static __device__ uint32_t g_Qh[(size_t)NH * QL * 32];          /* [nh][q][d/2]  */
static __device__ uint32_t g_Kh[(size_t)NH * KVL * 32];         /* [nh][kv][d/2] */
static __device__ uint32_t g_Vt[(size_t)NH * HD * (KVL / 2)];   /* [nh][d][rp]   */
static __device__ uint32_t g_Xh[(size_t)NBATCH * QL * (ED / 2)];/* attn out fp16 */
static __device__ uint32_t g_Wh[(size_t)ED * (ED / 2)];         /* W fp16        */
static __device__ uint32_t g_maskbits[NBATCH * QL * (KVL / 32)];

/* ----------------------------- small helpers ----------------------------- */
__device__ __forceinline__ uint32_t pack2(float lo, float hi) {
    __half2 h = __floats2half2_rn(lo, hi);
    return *(uint32_t*)&h;
}
__device__ __forceinline__ float ex2f(float x) {
    float r;
    asm("ex2.approx.f32 %0, %1;" : "=f"(r) : "f"(x));
    return r;
}
__device__ __forceinline__ uint32_t smem_u32(const void* p) {
    uint32_t a;
    asm("{ .reg .u64 t; cvta.to.shared.u64 t, %1; cvt.u32.u64 %0, t; }"
        : "=r"(a) : "l"(p));
    return a;
}
__device__ __forceinline__ void cp16(uint32_t dst, const void* src) {
    asm volatile("cp.async.cg.shared.global [%0], [%1], 16;"
                 :: "r"(dst), "l"(src) : "memory");
}
#define CP_COMMIT() asm volatile("cp.async.commit_group;" ::: "memory")
#define CP_WAIT0()  asm volatile("cp.async.wait_group 0;" ::: "memory")

/* warp-collective: 4x (8x8 b16) matrices, 1 reg each */
__device__ __forceinline__ void ldm4(uint32_t* r, uint32_t addr) {
    asm volatile("ldmatrix.sync.aligned.m8n8.x4.shared.b16 {%0,%1,%2,%3}, [%4];"
        : "=r"(r[0]), "=r"(r[1]), "=r"(r[2]), "=r"(r[3]) : "r"(addr));
}

/* D(16x8,f32) += A(16x16,f16) * B(16x8,f16)  —  m16n8k16 row.col */
__device__ __forceinline__ void mma16(float* d, const uint32_t* a,
                                      uint32_t b0, uint32_t b1) {
    asm volatile(
        "mma.sync.aligned.m16n8k16.row.col.f32.f16.f16.f32 "
        "{%0,%1,%2,%3}, {%4,%5,%6,%7}, {%8,%9}, {%0,%1,%2,%3};"
        : "+f"(d[0]), "+f"(d[1]), "+f"(d[2]), "+f"(d[3])
        : "r"(a[0]), "r"(a[1]), "r"(a[2]), "r"(a[3]), "r"(b0), "r"(b1));
}

/* ------------------------------ pre-kernels ------------------------------ */
__global__ void maskpack(const int* __restrict__ M) {
    int warpid = (blockIdx.x * blockDim.x + threadIdx.x) >> 5;
    int lane = threadIdx.x & 31;
    size_t base = (size_t)warpid * 8;
    #pragma unroll
    for (int t = 0; t < 8; t++) {
        size_t wd = base + t;
        int v = M[wd * 32 + lane];
        uint32_t bits = __ballot_sync(0xffffffffu, v != 0);
        if (lane == 0) g_maskbits[wd] = bits;
    }
}

__global__ __launch_bounds__(256) void convQK(const float* __restrict__ Q,
                                              const float* __restrict__ K) {
    int nh = blockIdx.y, n = nh >> 4, h = nh & 15;
    int r0 = blockIdx.x * 128;
    int tid = threadIdx.x;
    const float* qs = Q + ((size_t)n * QL + r0) * ED + h * HD;
    const float* ks = K + ((size_t)n * KVL + r0) * ED + h * HD;
    uint32_t* qd = g_Qh + ((size_t)nh * QL + r0) * 32;
    uint32_t* kd = g_Kh + ((size_t)nh * KVL + r0) * 32;
    #pragma unroll
    for (int j = 0; j < 8; j++) {
        int flat = tid + 256 * j, r = flat >> 4, d0 = (flat & 15) * 4;
        float4 a = *(const float4*)(qs + (size_t)r * ED + d0);
        qd[r * 32 + d0 / 2]     = pack2(a.x, a.y);
        qd[r * 32 + d0 / 2 + 1] = pack2(a.z, a.w);
        float4 b = *(const float4*)(ks + (size_t)r * ED + d0);
        kd[r * 32 + d0 / 2]     = pack2(b.x, b.y);
        kd[r * 32 + d0 / 2 + 1] = pack2(b.z, b.w);
    }
}

__global__ __launch_bounds__(256) void convV(const float* __restrict__ V) {
    int nh = blockIdx.y, n = nh >> 4, h = nh & 15;
    int rp = blockIdx.x * 32 + (threadIdx.x & 31);
    int w = threadIdx.x >> 5;
    const float* vs = V + (size_t)n * KVL * ED + h * HD;
    uint32_t* vd = g_Vt + (size_t)nh * HD * (KVL / 2);
    #pragma unroll
    for (int j = 0; j < 2; j++) {
        int d0 = (w * 2 + j) * 4;
        float4 a = *(const float4*)(vs + (size_t)(2 * rp) * ED + d0);
        float4 b = *(const float4*)(vs + (size_t)(2 * rp + 1) * ED + d0);
        vd[(d0 + 0) * (KVL / 2) + rp] = pack2(a.x, b.x);
        vd[(d0 + 1) * (KVL / 2) + rp] = pack2(a.y, b.y);
        vd[(d0 + 2) * (KVL / 2) + rp] = pack2(a.z, b.z);
        vd[(d0 + 3) * (KVL / 2) + rp] = pack2(a.w, b.w);
    }
}

__global__ void convW(const float* __restrict__ W) {
    int flat = blockIdx.x * 256 + threadIdx.x;
    float4 v = *(const float4*)(W + (size_t)flat * 4);
    g_Wh[flat * 2]     = pack2(v.x, v.y);
    g_Wh[flat * 2 + 1] = pack2(v.z, v.w);
}

/* -------------------- fp16 mma.sync flash attention ---------------------- */
/* BQ=128, 8 warps, occ 2. cp.async staging (R14). All in-loop fragment
   loads via ldmatrix.x4 (conflict-free at pitch 36). P register-resident.  */
__global__ __launch_bounds__(256, 2) void attn_mma() {
    extern __shared__ uint32_t sm[];
    uint32_t* QS  = sm + 9216;     /* [128][36] Q fragments     */
    const uint32_t sbase = smem_u32(sm);
    const uint32_t KSb = sbase;                 /* 2 K bufs @ 0, 9216 B    */
    const uint32_t VSb = sbase + 4608 * 4;      /* 2 V bufs                */
    const uint32_t QSb = sbase + 9216 * 4;

    const int tid = threadIdx.x, w = tid >> 5, lane = tid & 31;
    const int g = lane >> 2, c = lane & 3;
    const int lm = lane >> 3, lr = lane & 7;
    const int nh = blockIdx.y, n = nh >> 4;
    const int q0 = blockIdx.x * BQ;

    /* ldmatrix per-lane row offsets:
       QK: matrix m -> ks=m>>1, khalf=m&1 (words m>>1 *8 + (m&1)*4)
       PV: matrix m -> ds=+ (m>>1), khalf=m&1                              */
    const uint32_t qkOff = (uint32_t)lr * P4 + (lm >> 1) * 32 + (lm & 1) * 16;
    const uint32_t pvOff = (uint32_t)(lr + (lm >> 1) * 8) * P4 + (lm & 1) * 16;

    const uint32_t* Qg = g_Qh + ((size_t)nh * QL + q0) * 32;
    const uint32_t* Kg = g_Kh + (size_t)nh * KVL * 32;
    const uint32_t* Vg = g_Vt + (size_t)nh * HD * (KVL / 2);

    /* issue Q + K/V chunk 0 into buf 0 */
    #pragma unroll
    for (int i = 0; i < 4; i++) {
        int cid = tid + 256 * i, r = cid >> 3, seg = cid & 7;
        cp16(QSb + (r * PH_PITCH + seg * 4) * 4, Qg + r * 32 + seg * 4);
    }
    #pragma unroll
    for (int i = 0; i < 2; i++) {
        int cid = tid + 256 * i, r = cid >> 3, seg = cid & 7;
        cp16(KSb + (r * PH_PITCH + seg * 4) * 4, Kg + r * 32 + seg * 4);
        cp16(VSb + (r * PH_PITCH + seg * 4) * 4,
             Vg + (size_t)r * (KVL / 2) + seg * 4);
    }
    CP_COMMIT();
    CP_WAIT0();
    __syncthreads();

    /* resident Q A-fragments via ldmatrix (a0..a3 order matches mma16) */
    uint32_t aQ[4][4];
    {
        uint32_t aOff = (uint32_t)((lm & 1) * 8 + lr) * P4 + (lm >> 1) * 16;
        #pragma unroll
        for (int ks = 0; ks < 4; ks++)
            ldm4(aQ[ks], QSb + (w * 16) * P4 + ks * 32 + aOff);
    }

    float Oa[8][4];
    #pragma unroll
    for (int i = 0; i < 8; i++)
        #pragma unroll
        for (int j = 0; j < 4; j++) Oa[i][j] = 0.0f;
    float rs0 = 0.0f, rs1 = 0.0f;

    const unsigned long long* mbase = (const unsigned long long*)g_maskbits;
    const unsigned long long* mp0 =
        mbase + (size_t)(n * QL + q0 + w * 16 + g) * 32;
    const unsigned long long* mp1 = mp0 + 8 * 32;

    for (int ch = 0; ch < NCHUNK; ch++) {
        const int p = ch & 1;
        const uint32_t KSp = KSb + p * 9216;
        const uint32_t VSp = VSb + p * 9216;

        if (ch > 0) {
            CP_WAIT0();
            __syncthreads();
        }
        if (ch + 1 < NCHUNK) {
            const uint32_t kb2 = KSb + (1 - p) * 9216;
            const uint32_t vb2 = VSb + (1 - p) * 9216;
            const uint32_t* Kn = Kg + (size_t)(ch + 1) * 64 * 32;
            const uint32_t* Vn = Vg + (ch + 1) * 32;
            #pragma unroll
            for (int i = 0; i < 2; i++) {
                int cid = tid + 256 * i, r = cid >> 3, seg = cid & 7;
                cp16(kb2 + (r * PH_PITCH + seg * 4) * 4, Kn + r * 32 + seg * 4);
                cp16(vb2 + (r * PH_PITCH + seg * 4) * 4,
                     Vn + (size_t)r * (KVL / 2) + seg * 4);
            }
            CP_COMMIT();
        }

        unsigned long long m0 = mp0[ch];
        unsigned long long m1 = mp1[ch];

        /* ---- per nsp (16 kv): QK -> softmax (registers) -> PV */
        #pragma unroll
        for (int nsp = 0; nsp < 4; nsp++) {
            /* B-frags for both ns tiles: 4 ldmatrix.x4 */
            uint32_t B0[8], B1[8];
            {
                uint32_t a0 = KSp + (uint32_t)(2 * nsp) * (8 * P4) + qkOff;
                ldm4(B0, a0); ldm4(B0 + 4, a0 + 64);
                uint32_t a1 = a0 + 8 * P4;
                ldm4(B1, a1); ldm4(B1 + 4, a1 + 64);
            }

            float S[2][4];
            #pragma unroll
            for (int nn = 0; nn < 2; nn++)
                #pragma unroll
                for (int j = 0; j < 4; j++) S[nn][j] = 0.0f;

            #pragma unroll
            for (int ks = 0; ks < 4; ks++) {
                mma16(S[0], aQ[ks], B0[2 * ks], B0[2 * ks + 1]);
                mma16(S[1], aQ[ks], B1[2 * ks], B1[2 * ks + 1]);
            }

            uint32_t aP[4];
            #pragma unroll
            for (int nn = 0; nn < 2; nn++) {
                int ns = nsp * 2 + nn;
                int sh = ns * 8 + 2 * c;
                uint32_t bm0 = (uint32_t)(m0 >> sh);
                uint32_t bm1 = (uint32_t)(m1 >> sh);
                float e0 = (bm0 & 1u) ? ex2f(S[nn][0] * K2E) : 0.0f;
                float e1 = (bm0 & 2u) ? ex2f(S[nn][1] * K2E) : 0.0f;
                float e2 = (bm1 & 1u) ? ex2f(S[nn][2] * K2E) : 0.0f;
                float e3 = (bm1 & 2u) ? ex2f(S[nn][3] * K2E) : 0.0f;
                rs0 += e0 + e1;
                rs1 += e2 + e3;
                aP[2 * nn]     = pack2(e0, e1);
                aP[2 * nn + 1] = pack2(e2, e3);
            }

            /* PV B-frags: 4 ldmatrix.x4 cover ds 0..7 */
            uint32_t Vr[16];
            #pragma unroll
            for (int j = 0; j < 4; j++)
                ldm4(Vr + 4 * j, VSp + pvOff + (uint32_t)j * (16 * P4) + nsp * 32);
            #pragma unroll
            for (int ds = 0; ds < 8; ds++)
                mma16(Oa[ds], aP, Vr[2 * ds], Vr[2 * ds + 1]);
        }
    }

    /* row-sum reduce across quad, normalize, write fp16 to g_Xh */
    rs0 += __shfl_xor_sync(0xffffffffu, rs0, 1);
    rs0 += __shfl_xor_sync(0xffffffffu, rs0, 2);
    rs1 += __shfl_xor_sync(0xffffffffu, rs1, 1);
    rs1 += __shfl_xor_sync(0xffffffffu, rs1, 2);
    float inv0 = 1.0f / rs0, inv1 = 1.0f / rs1;

    uint32_t* x0 = g_Xh + (size_t)(n * QL + q0 + w * 16 + g) * 512
                 + (nh & 15) * 32;
    uint32_t* x1 = x0 + 8 * 512;
    #pragma unroll
    for (int ds = 0; ds < 8; ds++) {
        x0[ds * 4 + c] = pack2(Oa[ds][0] * inv0, Oa[ds][1] * inv0);
        x1[ds * 4 + c] = pack2(Oa[ds][2] * inv1, Oa[ds][3] * inv1);
    }
}

/* ------ projection Y = Xh Wh^T + b : cp.async + ldmatrix fragments ------- */
__global__ __launch_bounds__(256, 2) void proj_mma(const float* __restrict__ bias,
                                                   float* __restrict__ Y)
{
    extern __shared__ uint32_t ps[];
    const uint32_t sb = smem_u32(ps);
    const uint32_t XBb = sb, WBb = sb + 9216 * 4;

    const int tid = threadIdx.x, w = tid >> 5, lane = tid & 31;
    const int g = lane >> 2, c = lane & 3;
    const int lm = lane >> 3, lr = lane & 7;
    const int wm = w & 3, wn = w >> 2;
    const int m0 = blockIdx.y * 128, n0 = blockIdx.x * 128;

    const uint32_t aOff = (uint32_t)((lm & 1) * 8 + lr) * P4 + (lm >> 1) * 16;
    const uint32_t bOff = (uint32_t)((lm >> 1) * 8 + lr) * P4 + (lm & 1) * 16;

    const uint32_t* Xg = g_Xh + (size_t)m0 * 512;
    const uint32_t* Wg = g_Wh + (size_t)n0 * 512;

    float D[2][8][4];
    #pragma unroll
    for (int a = 0; a < 2; a++)
        #pragma unroll
        for (int i = 0; i < 8; i++)
            #pragma unroll
            for (int j = 0; j < 4; j++) D[a][i][j] = 0.0f;

    #pragma unroll
    for (int i = 0; i < 4; i++) {
        int cid = tid + 256 * i, r = cid >> 3, seg = cid & 7;
        cp16(XBb + (r * PH_PITCH + seg * 4) * 4, Xg + r * 512 + seg * 4);
        cp16(WBb + (r * PH_PITCH + seg * 4) * 4, Wg + r * 512 + seg * 4);
    }
    CP_COMMIT();

    for (int kt = 0; kt < 16; kt++) {
        const int p = kt & 1;
        CP_WAIT0();
        __syncthreads();
        if (kt + 1 < 16) {
            const uint32_t xb2 = XBb + (1 - p) * 4608 * 4;
            const uint32_t wb2 = WBb + (1 - p) * 4608 * 4;
            int koff = (kt + 1) * 32;
            #pragma unroll
            for (int i = 0; i < 4; i++) {
                int cid = tid + 256 * i, r = cid >> 3, seg = cid & 7;
                cp16(xb2 + (r * PH_PITCH + seg * 4) * 4,
                     Xg + r * 512 + koff + seg * 4);
                cp16(wb2 + (r * PH_PITCH + seg * 4) * 4,
                     Wg + r * 512 + koff + seg * 4);
            }
            CP_COMMIT();
        }

        const uint32_t XSp = XBb + p * 4608 * 4;
        const uint32_t WSp = WBb + p * 4608 * 4;
        #pragma unroll
        for (int ks = 0; ks < 4; ks++) {
            uint32_t A0[4], A1[4];
            ldm4(A0, XSp + (uint32_t)(wm * 32) * P4 + ks * 32 + aOff);
            ldm4(A1, XSp + (uint32_t)(wm * 32 + 16) * P4 + ks * 32 + aOff);
            uint32_t Wr[16];
            #pragma unroll
            for (int j = 0; j < 4; j++)
                ldm4(Wr + 4 * j,
                     WSp + (uint32_t)(wn * 64 + j * 16) * P4 + ks * 32 + bOff);
            #pragma unroll
            for (int ns = 0; ns < 8; ns++) {
                mma16(D[0][ns], A0, Wr[2 * ns], Wr[2 * ns + 1]);
                mma16(D[1][ns], A1, Wr[2 * ns], Wr[2 * ns + 1]);
            }
        }
        __syncthreads();   /* reads of buf p done before its next overwrite */
    }

    #pragma unroll
    for (int mi = 0; mi < 2; mi++) {
        int row0 = m0 + wm * 32 + mi * 16 + g;
        #pragma unroll
        for (int ns = 0; ns < 8; ns++) {
            int col = n0 + wn * 64 + ns * 8 + 2 * c;
            float2 bv = *(const float2*)(bias + col);
            *(float2*)(Y + (size_t)row0 * ED + col) =
                make_float2(D[mi][ns][0] + bv.x, D[mi][ns][1] + bv.y);
            *(float2*)(Y + (size_t)(row0 + 8) * ED + col) =
                make_float2(D[mi][ns][2] + bv.x, D[mi][ns][3] + bv.y);
        }
    }
}

/* --------------------------------- launch -------------------------------- */
extern "C" void kernel_launch(void* const* d_in, const int* in_sizes, int n_in,
                              void* d_out, int out_size)
{
    const float* q    = (const float*)d_in[0];
    const float* k    = (const float*)d_in[1];
    const float* v    = (const float*)d_in[2];
    const int*   mask = (const int*)  d_in[3];
    const float* W    = (const float*)d_in[4];
    const float* b    = (const float*)d_in[5];
    float* out = (float*)d_out;

    const int smem_attn = 13824 * 4;   /* 55296 */
    const int smem_proj = 18432 * 4;   /* 73728 */
    cudaFuncSetAttribute(attn_mma, cudaFuncAttributeMaxDynamicSharedMemorySize, smem_attn);
    cudaFuncSetAttribute(proj_mma, cudaFuncAttributeMaxDynamicSharedMemorySize, smem_proj);

    maskpack<<<8192, 256>>>(mask);
    convQK<<<dim3(16, 64), 256>>>(q, k);
    convV<<<dim3(32, 64), 256>>>(v);
    convW<<<1024, 256>>>(W);

    attn_mma<<<dim3(QL / BQ, NH), 256, smem_attn>>>();

    proj_mma<<<dim3(ED / 128, (NBATCH * QL) / 128), 256, smem_proj>>>(b, out);
}

// round 17
// speedup vs baseline: 1.1384x; 1.0213x over previous
#include <cuda_runtime.h>
#include <cuda_fp16.h>
#include <cstdint>

#define NBATCH 4
#define HEADS  16
#define NH     (NBATCH * HEADS)
#define QL     2048
#define KVL    2048
#define HD     64
#define ED     1024
#define K2E    0.045084220027780106f   /* (1/sqrt(1024)) * log2(e) */

#define BQ 128
#define BN 64
#define NCHUNK (KVL / BN)
#define PH_PITCH 36   /* words (half2 pairs); %32==4 -> conflict-free ldmatrix */
#define P4 (PH_PITCH * 4)

/* pre-converted fp16 operand layouts (device scratch) */
static __device__ uint32_t g_Qh[(size_t)NH * QL * 32];          /* [nh][q][d/2]  */
static __device__ uint32_t g_Kh[(size_t)NH * KVL * 32];         /* [nh][kv][d/2] */
static __device__ uint32_t g_Vt[(size_t)NH * HD * (KVL / 2)];   /* [nh][d][rp]   */
static __device__ uint32_t g_Xh[(size_t)NBATCH * QL * (ED / 2)];/* attn out fp16 */
static __device__ uint32_t g_Wh[(size_t)ED * (ED / 2)];         /* W fp16        */
static __device__ uint32_t g_maskbits[NBATCH * QL * (KVL / 32)];

/* ----------------------------- small helpers ----------------------------- */
__device__ __forceinline__ uint32_t pack2(float lo, float hi) {
    __half2 h = __floats2half2_rn(lo, hi);
    return *(uint32_t*)&h;
}
__device__ __forceinline__ float ex2f(float x) {
    float r;
    asm("ex2.approx.f32 %0, %1;" : "=f"(r) : "f"(x));
    return r;
}
__device__ __forceinline__ uint32_t smem_u32(const void* p) {
    uint32_t a;
    asm("{ .reg .u64 t; cvta.to.shared.u64 t, %1; cvt.u32.u64 %0, t; }"
        : "=r"(a) : "l"(p));
    return a;
}
__device__ __forceinline__ void cp16(uint32_t dst, const void* src) {
    asm volatile("cp.async.cg.shared.global [%0], [%1], 16;"
                 :: "r"(dst), "l"(src) : "memory");
}
#define CP_COMMIT() asm volatile("cp.async.commit_group;" ::: "memory")
#define CP_WAIT0()  asm volatile("cp.async.wait_group 0;" ::: "memory")

/* warp-collective: 4x (8x8 b16) matrices, 1 reg each */
__device__ __forceinline__ void ldm4(uint32_t* r, uint32_t addr) {
    asm volatile("ldmatrix.sync.aligned.m8n8.x4.shared.b16 {%0,%1,%2,%3}, [%4];"
        : "=r"(r[0]), "=r"(r[1]), "=r"(r[2]), "=r"(r[3]) : "r"(addr));
}

/* D(16x8,f32) += A(16x16,f16) * B(16x8,f16)  —  m16n8k16 row.col */
__device__ __forceinline__ void mma16(float* d, const uint32_t* a,
                                      uint32_t b0, uint32_t b1) {
    asm volatile(
        "mma.sync.aligned.m16n8k16.row.col.f32.f16.f16.f32 "
        "{%0,%1,%2,%3}, {%4,%5,%6,%7}, {%8,%9}, {%0,%1,%2,%3};"
        : "+f"(d[0]), "+f"(d[1]), "+f"(d[2]), "+f"(d[3])
        : "r"(a[0]), "r"(a[1]), "r"(a[2]), "r"(a[3]), "r"(b0), "r"(b1));
}

/* ------------------------------ pre-kernels ------------------------------ */
__global__ void maskpack(const int* __restrict__ M) {
    int warpid = (blockIdx.x * blockDim.x + threadIdx.x) >> 5;
    int lane = threadIdx.x & 31;
    size_t base = (size_t)warpid * 8;
    #pragma unroll
    for (int t = 0; t < 8; t++) {
        size_t wd = base + t;
        int v = M[wd * 32 + lane];
        uint32_t bits = __ballot_sync(0xffffffffu, v != 0);
        if (lane == 0) g_maskbits[wd] = bits;
    }
}

__global__ __launch_bounds__(256) void convQK(const float* __restrict__ Q,
                                              const float* __restrict__ K) {
    int nh = blockIdx.y, n = nh >> 4, h = nh & 15;
    int r0 = blockIdx.x * 128;
    int tid = threadIdx.x;
    const float* qs = Q + ((size_t)n * QL + r0) * ED + h * HD;
    const float* ks = K + ((size_t)n * KVL + r0) * ED + h * HD;
    uint32_t* qd = g_Qh + ((size_t)nh * QL + r0) * 32;
    uint32_t* kd = g_Kh + ((size_t)nh * KVL + r0) * 32;
    #pragma unroll
    for (int j = 0; j < 8; j++) {
        int flat = tid + 256 * j, r = flat >> 4, d0 = (flat & 15) * 4;
        float4 a = *(const float4*)(qs + (size_t)r * ED + d0);
        qd[r * 32 + d0 / 2]     = pack2(a.x, a.y);
        qd[r * 32 + d0 / 2 + 1] = pack2(a.z, a.w);
        float4 b = *(const float4*)(ks + (size_t)r * ED + d0);
        kd[r * 32 + d0 / 2]     = pack2(b.x, b.y);
        kd[r * 32 + d0 / 2 + 1] = pack2(b.z, b.w);
    }
}

__global__ __launch_bounds__(256) void convV(const float* __restrict__ V) {
    int nh = blockIdx.y, n = nh >> 4, h = nh & 15;
    int rp = blockIdx.x * 32 + (threadIdx.x & 31);
    int w = threadIdx.x >> 5;
    const float* vs = V + (size_t)n * KVL * ED + h * HD;
    uint32_t* vd = g_Vt + (size_t)nh * HD * (KVL / 2);
    #pragma unroll
    for (int j = 0; j < 2; j++) {
        int d0 = (w * 2 + j) * 4;
        float4 a = *(const float4*)(vs + (size_t)(2 * rp) * ED + d0);
        float4 b = *(const float4*)(vs + (size_t)(2 * rp + 1) * ED + d0);
        vd[(d0 + 0) * (KVL / 2) + rp] = pack2(a.x, b.x);
        vd[(d0 + 1) * (KVL / 2) + rp] = pack2(a.y, b.y);
        vd[(d0 + 2) * (KVL / 2) + rp] = pack2(a.z, b.z);
        vd[(d0 + 3) * (KVL / 2) + rp] = pack2(a.w, b.w);
    }
}

__global__ void convW(const float* __restrict__ W) {
    int flat = blockIdx.x * 256 + threadIdx.x;
    float4 v = *(const float4*)(W + (size_t)flat * 4);
    g_Wh[flat * 2]     = pack2(v.x, v.y);
    g_Wh[flat * 2 + 1] = pack2(v.z, v.w);
}

/* -------------------- fp16 mma.sync flash attention ---------------------- */
/* BQ=128, 8 warps, occ 2. Register-pipelined fragments: V frags loaded
   before QK (hidden under QK MMAs); next-nsp K frags prefetched before
   softmax (hidden under softmax+PV). LDS and tensor pipes overlap.         */
__global__ __launch_bounds__(256, 2) void attn_mma() {
    extern __shared__ uint32_t sm[];
    const uint32_t sbase = smem_u32(sm);
    const uint32_t KSb = sbase;                 /* 2 K bufs @ 0, 9216 B    */
    const uint32_t VSb = sbase + 4608 * 4;      /* 2 V bufs                */
    const uint32_t QSb = sbase + 9216 * 4;

    const int tid = threadIdx.x, w = tid >> 5, lane = tid & 31;
    const int g = lane >> 2, c = lane & 3;
    const int lm = lane >> 3, lr = lane & 7;
    const int nh = blockIdx.y, n = nh >> 4;
    const int q0 = blockIdx.x * BQ;

    const uint32_t qkOff = (uint32_t)lr * P4 + (lm >> 1) * 32 + (lm & 1) * 16;
    const uint32_t pvOff = (uint32_t)(lr + (lm >> 1) * 8) * P4 + (lm & 1) * 16;

    const uint32_t* Qg = g_Qh + ((size_t)nh * QL + q0) * 32;
    const uint32_t* Kg = g_Kh + (size_t)nh * KVL * 32;
    const uint32_t* Vg = g_Vt + (size_t)nh * HD * (KVL / 2);

    /* issue Q + K/V chunk 0 into buf 0 */
    #pragma unroll
    for (int i = 0; i < 4; i++) {
        int cid = tid + 256 * i, r = cid >> 3, seg = cid & 7;
        cp16(QSb + (r * PH_PITCH + seg * 4) * 4, Qg + r * 32 + seg * 4);
    }
    #pragma unroll
    for (int i = 0; i < 2; i++) {
        int cid = tid + 256 * i, r = cid >> 3, seg = cid & 7;
        cp16(KSb + (r * PH_PITCH + seg * 4) * 4, Kg + r * 32 + seg * 4);
        cp16(VSb + (r * PH_PITCH + seg * 4) * 4,
             Vg + (size_t)r * (KVL / 2) + seg * 4);
    }
    CP_COMMIT();
    CP_WAIT0();
    __syncthreads();

    /* resident Q A-fragments via ldmatrix */
    uint32_t aQ[4][4];
    {
        uint32_t aOff = (uint32_t)((lm & 1) * 8 + lr) * P4 + (lm >> 1) * 16;
        #pragma unroll
        for (int ks = 0; ks < 4; ks++)
            ldm4(aQ[ks], QSb + (w * 16) * P4 + ks * 32 + aOff);
    }

    float Oa[8][4];
    #pragma unroll
    for (int i = 0; i < 8; i++)
        #pragma unroll
        for (int j = 0; j < 4; j++) Oa[i][j] = 0.0f;
    float rs0 = 0.0f, rs1 = 0.0f;

    const unsigned long long* mbase = (const unsigned long long*)g_maskbits;
    const unsigned long long* mp0 =
        mbase + (size_t)(n * QL + q0 + w * 16 + g) * 32;
    const unsigned long long* mp1 = mp0 + 8 * 32;

    for (int ch = 0; ch < NCHUNK; ch++) {
        const int p = ch & 1;
        const uint32_t KSp = KSb + p * 9216;
        const uint32_t VSp = VSb + p * 9216;

        if (ch > 0) {
            CP_WAIT0();
            __syncthreads();
        }
        if (ch + 1 < NCHUNK) {
            const uint32_t kb2 = KSb + (1 - p) * 9216;
            const uint32_t vb2 = VSb + (1 - p) * 9216;
            const uint32_t* Kn = Kg + (size_t)(ch + 1) * 64 * 32;
            const uint32_t* Vn = Vg + (ch + 1) * 32;
            #pragma unroll
            for (int i = 0; i < 2; i++) {
                int cid = tid + 256 * i, r = cid >> 3, seg = cid & 7;
                cp16(kb2 + (r * PH_PITCH + seg * 4) * 4, Kn + r * 32 + seg * 4);
                cp16(vb2 + (r * PH_PITCH + seg * 4) * 4,
                     Vn + (size_t)r * (KVL / 2) + seg * 4);
            }
            CP_COMMIT();
        }

        unsigned long long m0 = mp0[ch];
        unsigned long long m1 = mp1[ch];

        /* preload K B-frags for nsp=0 */
        uint32_t Bc[16];
        {
            uint32_t a0 = KSp + qkOff;
            ldm4(Bc, a0);      ldm4(Bc + 4, a0 + 64);
            uint32_t a1 = a0 + 8 * P4;
            ldm4(Bc + 8, a1);  ldm4(Bc + 12, a1 + 64);
        }

        /* ---- per nsp (16 kv), register-pipelined */
        #pragma unroll
        for (int nsp = 0; nsp < 4; nsp++) {
            /* V frags early — consumed only after softmax */
            uint32_t Vr[16];
            #pragma unroll
            for (int j = 0; j < 4; j++)
                ldm4(Vr + 4 * j,
                     VSp + pvOff + (uint32_t)j * (16 * P4) + nsp * 32);

            float S[2][4];
            #pragma unroll
            for (int nn = 0; nn < 2; nn++)
                #pragma unroll
                for (int j = 0; j < 4; j++) S[nn][j] = 0.0f;

            #pragma unroll
            for (int ks = 0; ks < 4; ks++) {
                mma16(S[0], aQ[ks], Bc[2 * ks],     Bc[2 * ks + 1]);
                mma16(S[1], aQ[ks], Bc[8 + 2 * ks], Bc[8 + 2 * ks + 1]);
            }

            /* prefetch next nsp's K frags — hidden under softmax + PV */
            uint32_t Bn[16];
            if (nsp < 3) {
                uint32_t a0 = KSp + (uint32_t)(2 * (nsp + 1)) * (8 * P4) + qkOff;
                ldm4(Bn, a0);      ldm4(Bn + 4, a0 + 64);
                uint32_t a1 = a0 + 8 * P4;
                ldm4(Bn + 8, a1);  ldm4(Bn + 12, a1 + 64);
            }

            uint32_t aP[4];
            #pragma unroll
            for (int nn = 0; nn < 2; nn++) {
                int ns = nsp * 2 + nn;
                int sh = ns * 8 + 2 * c;
                uint32_t bm0 = (uint32_t)(m0 >> sh);
                uint32_t bm1 = (uint32_t)(m1 >> sh);
                float e0 = (bm0 & 1u) ? ex2f(S[nn][0] * K2E) : 0.0f;
                float e1 = (bm0 & 2u) ? ex2f(S[nn][1] * K2E) : 0.0f;
                float e2 = (bm1 & 1u) ? ex2f(S[nn][2] * K2E) : 0.0f;
                float e3 = (bm1 & 2u) ? ex2f(S[nn][3] * K2E) : 0.0f;
                rs0 += e0 + e1;
                rs1 += e2 + e3;
                aP[2 * nn]     = pack2(e0, e1);
                aP[2 * nn + 1] = pack2(e2, e3);
            }

            #pragma unroll
            for (int ds = 0; ds < 8; ds++)
                mma16(Oa[ds], aP, Vr[2 * ds], Vr[2 * ds + 1]);

            if (nsp < 3) {
                #pragma unroll
                for (int j = 0; j < 16; j++) Bc[j] = Bn[j];
            }
        }
    }

    /* row-sum reduce across quad, normalize, write fp16 to g_Xh */
    rs0 += __shfl_xor_sync(0xffffffffu, rs0, 1);
    rs0 += __shfl_xor_sync(0xffffffffu, rs0, 2);
    rs1 += __shfl_xor_sync(0xffffffffu, rs1, 1);
    rs1 += __shfl_xor_sync(0xffffffffu, rs1, 2);
    float inv0 = 1.0f / rs0, inv1 = 1.0f / rs1;

    uint32_t* x0 = g_Xh + (size_t)(n * QL + q0 + w * 16 + g) * 512
                 + (nh & 15) * 32;
    uint32_t* x1 = x0 + 8 * 512;
    #pragma unroll
    for (int ds = 0; ds < 8; ds++) {
        x0[ds * 4 + c] = pack2(Oa[ds][0] * inv0, Oa[ds][1] * inv0);
        x1[ds * 4 + c] = pack2(Oa[ds][2] * inv1, Oa[ds][3] * inv1);
    }
}

/* ------ projection Y = Xh Wh^T + b : cp.async + pipelined ldmatrix ------- */
__global__ __launch_bounds__(256, 2) void proj_mma(const float* __restrict__ bias,
                                                   float* __restrict__ Y)
{
    extern __shared__ uint32_t ps[];
    const uint32_t sb = smem_u32(ps);
    const uint32_t XBb = sb, WBb = sb + 9216 * 4;

    const int tid = threadIdx.x, w = tid >> 5, lane = tid & 31;
    const int g = lane >> 2, c = lane & 3;
    const int lm = lane >> 3, lr = lane & 7;
    const int wm = w & 3, wn = w >> 2;
    const int m0 = blockIdx.y * 128, n0 = blockIdx.x * 128;

    const uint32_t aOff = (uint32_t)((lm & 1) * 8 + lr) * P4 + (lm >> 1) * 16;
    const uint32_t bOff = (uint32_t)((lm >> 1) * 8 + lr) * P4 + (lm & 1) * 16;

    const uint32_t* Xg = g_Xh + (size_t)m0 * 512;
    const uint32_t* Wg = g_Wh + (size_t)n0 * 512;

    float D[2][8][4];
    #pragma unroll
    for (int a = 0; a < 2; a++)
        #pragma unroll
        for (int i = 0; i < 8; i++)
            #pragma unroll
            for (int j = 0; j < 4; j++) D[a][i][j] = 0.0f;

    #pragma unroll
    for (int i = 0; i < 4; i++) {
        int cid = tid + 256 * i, r = cid >> 3, seg = cid & 7;
        cp16(XBb + (r * PH_PITCH + seg * 4) * 4, Xg + r * 512 + seg * 4);
        cp16(WBb + (r * PH_PITCH + seg * 4) * 4, Wg + r * 512 + seg * 4);
    }
    CP_COMMIT();

    for (int kt = 0; kt < 16; kt++) {
        const int p = kt & 1;
        CP_WAIT0();
        __syncthreads();
        if (kt + 1 < 16) {
            const uint32_t xb2 = XBb + (1 - p) * 4608 * 4;
            const uint32_t wb2 = WBb + (1 - p) * 4608 * 4;
            int koff = (kt + 1) * 32;
            #pragma unroll
            for (int i = 0; i < 4; i++) {
                int cid = tid + 256 * i, r = cid >> 3, seg = cid & 7;
                cp16(xb2 + (r * PH_PITCH + seg * 4) * 4,
                     Xg + r * 512 + koff + seg * 4);
                cp16(wb2 + (r * PH_PITCH + seg * 4) * 4,
                     Wg + r * 512 + koff + seg * 4);
            }
            CP_COMMIT();
        }

        const uint32_t XSp = XBb + p * 4608 * 4;
        const uint32_t WSp = WBb + p * 4608 * 4;

        /* preload ks=0 fragments */
        uint32_t A0[4], A1[4], Wr[16];
        ldm4(A0, XSp + (uint32_t)(wm * 32) * P4 + aOff);
        ldm4(A1, XSp + (uint32_t)(wm * 32 + 16) * P4 + aOff);
        #pragma unroll
        for (int j = 0; j < 4; j++)
            ldm4(Wr + 4 * j, WSp + (uint32_t)(wn * 64 + j * 16) * P4 + bOff);

        #pragma unroll
        for (int ks = 0; ks < 4; ks++) {
            /* prefetch ks+1 fragments — hidden under the 16 MMAs below */
            uint32_t A0n[4], A1n[4], Wn[16];
            if (ks < 3) {
                uint32_t ko = (uint32_t)(ks + 1) * 32;
                ldm4(A0n, XSp + (uint32_t)(wm * 32) * P4 + ko + aOff);
                ldm4(A1n, XSp + (uint32_t)(wm * 32 + 16) * P4 + ko + aOff);
                #pragma unroll
                for (int j = 0; j < 4; j++)
                    ldm4(Wn + 4 * j,
                         WSp + (uint32_t)(wn * 64 + j * 16) * P4 + ko + bOff);
            }
            #pragma unroll
            for (int ns = 0; ns < 8; ns++) {
                mma16(D[0][ns], A0, Wr[2 * ns], Wr[2 * ns + 1]);
                mma16(D[1][ns], A1, Wr[2 * ns], Wr[2 * ns + 1]);
            }
            if (ks < 3) {
                #pragma unroll
                for (int j = 0; j < 4; j++) { A0[j] = A0n[j]; A1[j] = A1n[j]; }
                #pragma unroll
                for (int j = 0; j < 16; j++) Wr[j] = Wn[j];
            }
        }
        __syncthreads();   /* reads of buf p done before its next overwrite */
    }

    #pragma unroll
    for (int mi = 0; mi < 2; mi++) {
        int row0 = m0 + wm * 32 + mi * 16 + g;
        #pragma unroll
        for (int ns = 0; ns < 8; ns++) {
            int col = n0 + wn * 64 + ns * 8 + 2 * c;
            float2 bv = *(const float2*)(bias + col);
            *(float2*)(Y + (size_t)row0 * ED + col) =
                make_float2(D[mi][ns][0] + bv.x, D[mi][ns][1] + bv.y);
            *(float2*)(Y + (size_t)(row0 + 8) * ED + col) =
                make_float2(D[mi][ns][2] + bv.x, D[mi][ns][3] + bv.y);
        }
    }
}

/* --------------------------------- launch -------------------------------- */
extern "C" void kernel_launch(void* const* d_in, const int* in_sizes, int n_in,
                              void* d_out, int out_size)
{
    const float* q    = (const float*)d_in[0];
    const float* k    = (const float*)d_in[1];
    const float* v    = (const float*)d_in[2];
    const int*   mask = (const int*)  d_in[3];
    const float* W    = (const float*)d_in[4];
    const float* b    = (const float*)d_in[5];
    float* out = (float*)d_out;

    const int smem_attn = 13824 * 4;   /* 55296 */
    const int smem_proj = 18432 * 4;   /* 73728 */
    cudaFuncSetAttribute(attn_mma, cudaFuncAttributeMaxDynamicSharedMemorySize, smem_attn);
    cudaFuncSetAttribute(proj_mma, cudaFuncAttributeMaxDynamicSharedMemorySize, smem_proj);

    maskpack<<<8192, 256>>>(mask);
    convQK<<<dim3(16, 64), 256>>>(q, k);
    convV<<<dim3(32, 64), 256>>>(v);
    convW<<<1024, 256>>>(W);

    attn_mma<<<dim3(QL / BQ, NH), 256, smem_attn>>>();

    proj_mma<<<dim3(ED / 128, (NBATCH * QL) / 128), 256, smem_proj>>>(b, out);
}